// round 4
// baseline (speedup 1.0000x reference)
#include <cuda_runtime.h>
#include <cuda_bf16.h>
#include <math.h>

#define ROWS 4096          // B*S = 2*2048
#define DM   1024
#define KW   256           // 1024/4 packed words per row
#define NELEM (ROWS*DM)

typedef unsigned int u32;
typedef unsigned long long ull;

// ------------------------- static device scratch (no allocs) -------------
__device__ float  g_xn[4][NELEM];       // layernorm outputs (q,k,v,attn)
__device__ u32    g_xq[4][ROWS*KW];     // int8-packed quantized activations
__device__ u32    g_wq[4][DM*KW];       // int8-packed sign weights
__device__ float  g_proj[3][NELEM];     // qp/kp/vp projections (fp32)
__device__ float  g_att[NELEM];         // attention output (concat heads)
__device__ double g_wpart[4][256][2];   // weight-stat partials (double)
__device__ double g_wmean[4];
__device__ float  g_wbeta[4];
__device__ u32    g_absmax[4];          // float bits, atomicMax as uint
__device__ u32    g_maskbits[ROWS*64];  // bit-packed mask, 2048 bits/row

// ------------------------- f32x2 packed helpers --------------------------
__device__ __forceinline__ ull pk2(float lo, float hi){
  ull r; asm("mov.b64 %0,{%1,%2};" : "=l"(r) : "f"(lo), "f"(hi)); return r;
}
__device__ __forceinline__ float2 upk2(ull v){
  float2 f; asm("mov.b64 {%0,%1},%2;" : "=f"(f.x), "=f"(f.y) : "l"(v)); return f;
}
__device__ __forceinline__ ull f2fma(ull a, ull b, ull c){
  ull r; asm("fma.rn.f32x2 %0,%1,%2,%3;" : "=l"(r) : "l"(a), "l"(b), "l"(c)); return r;
}
__device__ __forceinline__ ull f2mul(ull a, ull b){
  ull r; asm("mul.rn.f32x2 %0,%1,%2;" : "=l"(r) : "l"(a), "l"(b)); return r;
}
__device__ __forceinline__ ull f2add(ull a, ull b){
  ull r; asm("add.rn.f32x2 %0,%1,%2;" : "=l"(r) : "l"(a), "l"(b)); return r;
}

// ------------------------- reductions ------------------------------------
__device__ __forceinline__ double blockRedD(double v, double* sh){
  #pragma unroll
  for (int o=16;o;o>>=1) v += __shfl_xor_sync(0xffffffffu, v, o);
  if ((threadIdx.x & 31) == 0) sh[threadIdx.x>>5] = v;
  __syncthreads();
  if (threadIdx.x == 0){
    double r = sh[0];
    #pragma unroll
    for (int i=1;i<8;i++) r += sh[i];
    sh[0] = r;
  }
  __syncthreads();
  double r = sh[0];
  __syncthreads();
  return r;
}
__device__ __forceinline__ float blockMaxF(float v, float* sh){
  #pragma unroll
  for (int o=16;o;o>>=1) v = fmaxf(v, __shfl_xor_sync(0xffffffffu, v, o));
  if ((threadIdx.x & 31) == 0) sh[threadIdx.x>>5] = v;
  __syncthreads();
  if (threadIdx.x == 0){
    float r = sh[0];
    #pragma unroll
    for (int i=1;i<8;i++) r = fmaxf(r, sh[i]);
    sh[0] = r;
  }
  __syncthreads();
  float r = sh[0];
  __syncthreads();
  return r;
}

// ------------------------- kernels ---------------------------------------
__global__ void k_init(){
  if (threadIdx.x < 4) g_absmax[threadIdx.x] = 0u;
}

__global__ void k_wstats1(const float* w0, const float* w1,
                          const float* w2, const float* w3){
  const float* w = (blockIdx.y==0)?w0 : (blockIdx.y==1)?w1 : (blockIdx.y==2)?w2 : w3;
  int base = blockIdx.x * 4096;
  double s = 0.0, a = 0.0;
  for (int i = threadIdx.x; i < 4096; i += 256){
    double v = (double)w[base + i]; s += v; a += fabs(v);
  }
  __shared__ double shs[8], sha[8];
  #pragma unroll
  for (int o=16;o;o>>=1){
    s += __shfl_xor_sync(0xffffffffu, s, o);
    a += __shfl_xor_sync(0xffffffffu, a, o);
  }
  if ((threadIdx.x & 31) == 0){ shs[threadIdx.x>>5] = s; sha[threadIdx.x>>5] = a; }
  __syncthreads();
  if (threadIdx.x == 0){
    double S=0.0, A=0.0;
    #pragma unroll
    for (int i=0;i<8;i++){ S += shs[i]; A += sha[i]; }
    g_wpart[blockIdx.y][blockIdx.x][0] = S;
    g_wpart[blockIdx.y][blockIdx.x][1] = A;
  }
}

__global__ void k_wstats2(){
  int wh = blockIdx.x;
  double s = g_wpart[wh][threadIdx.x][0];
  double a = g_wpart[wh][threadIdx.x][1];
  __shared__ double shs[8], sha[8];
  #pragma unroll
  for (int o=16;o;o>>=1){
    s += __shfl_xor_sync(0xffffffffu, s, o);
    a += __shfl_xor_sync(0xffffffffu, a, o);
  }
  if ((threadIdx.x & 31) == 0){ shs[threadIdx.x>>5] = s; sha[threadIdx.x>>5] = a; }
  __syncthreads();
  if (threadIdx.x == 0){
    double S=0.0, A=0.0;
    #pragma unroll
    for (int i=0;i<8;i++){ S += shs[i]; A += sha[i]; }
    g_wmean[wh] = S * (1.0/1048576.0);
    g_wbeta[wh] = (float)(A * (1.0/1048576.0));
  }
}

__device__ __forceinline__ int sgn3d(double x, double mu){
  return (x > mu) ? 1 : ((x < mu) ? -1 : 0);
}

__global__ void k_wquant(const float* w0, const float* w1,
                         const float* w2, const float* w3){
  int wh = blockIdx.y;
  const float* w = (wh==0)?w0 : (wh==1)?w1 : (wh==2)?w2 : w3;
  double mu = g_wmean[wh];
  int o = blockIdx.x;
  float4 v = ((const float4*)(w + (size_t)o*DM))[threadIdx.x];
  int a = sgn3d((double)v.x,mu), b = sgn3d((double)v.y,mu);
  int c = sgn3d((double)v.z,mu), d = sgn3d((double)v.w,mu);
  g_wq[wh][(size_t)o*KW + threadIdx.x] =
      (u32)(a & 0xff) | ((u32)(b & 0xff) << 8) |
      ((u32)(c & 0xff) << 16) | ((u32)(d & 0xff) << 24);
}

// LayerNorm in full double precision (mean, var, normalize), rounded once to f32.
__global__ void k_ln(const float* X, int slot){
  __shared__ double shd[8];
  __shared__ float shf[8];
  const float* src = (slot == 3) ? g_att : X;
  int row = blockIdx.x;
  float4 v = ((const float4*)(src + (size_t)row*DM))[threadIdx.x];
  double s = (double)v.x + (double)v.y + (double)v.z + (double)v.w;
  s = blockRedD(s, shd);
  double mu = s * (1.0/1024.0);
  double ax = (double)v.x - mu, ay = (double)v.y - mu;
  double az = (double)v.z - mu, aw = (double)v.w - mu;
  double ss = ax*ax + ay*ay + az*az + aw*aw;
  ss = blockRedD(ss, shd);
  double var = ss * (1.0/1024.0) + 1e-5;
  double r = 1.0 / sqrt(var);
  float4 o;
  o.x = (float)(ax*r); o.y = (float)(ay*r);
  o.z = (float)(az*r); o.w = (float)(aw*r);
  ((float4*)(g_xn[slot] + (size_t)row*DM))[threadIdx.x] = o;
  float am = fmaxf(fmaxf(fabsf(o.x), fabsf(o.y)), fmaxf(fabsf(o.z), fabsf(o.w)));
  am = blockMaxF(am, shf);
  if (threadIdx.x == 0) atomicMax(&g_absmax[slot], __float_as_uint(am));
}

__device__ __forceinline__ int qv(float x, float qs){
  int v = (int)rintf(x * qs);        // RN = round half to even, matches jnp.round
  return (v == 128) ? -128 : v;      // int8 wrap of the +128 element
}

__global__ void k_quant(int slot){
  int row = blockIdx.x;
  float mx = __uint_as_float(g_absmax[slot]);
  float qs = 128.0f / mx;
  float4 v = ((const float4*)(g_xn[slot] + (size_t)row*DM))[threadIdx.x];
  int a = qv(v.x,qs), b = qv(v.y,qs), c = qv(v.z,qs), d = qv(v.w,qs);
  g_xq[slot][(size_t)row*KW + threadIdx.x] =
      (u32)(a & 0xff) | ((u32)(b & 0xff) << 8) |
      ((u32)(c & 0xff) << 16) | ((u32)(d & 0xff) << 24);
}

// int8 dp4a GEMM: C[r][o] = sum_i xq[r][i] * wq[o][i], exact in int32.
__global__ void __launch_bounds__(256) k_gemm(float* Cext, int slot0){
  int slot = slot0 + blockIdx.z;
  const u32* X = g_xq[slot];
  const u32* W = g_wq[slot];
  float* C = (slot < 3) ? g_proj[slot] : Cext;
  int m0 = blockIdx.y * 64, n0 = blockIdx.x * 64;
  __shared__ u32 As[64*20], Bs[64*20];   // stride 20 words kills .128 conflicts
  int tid = threadIdx.x;
  int tx = tid & 15, ty = tid >> 4;
  int lrow = tid >> 2, lc = (tid & 3) * 4;
  int acc[4][4];
  #pragma unroll
  for (int m=0;m<4;m++)
    #pragma unroll
    for (int n=0;n<4;n++) acc[m][n] = 0;

  for (int kt = 0; kt < 16; kt++){
    uint4 xa = *(const uint4*)(X + (size_t)(m0+lrow)*KW + kt*16 + lc);
    uint4 wb = *(const uint4*)(W + (size_t)(n0+lrow)*KW + kt*16 + lc);
    *(uint4*)&As[lrow*20 + lc] = xa;
    *(uint4*)&Bs[lrow*20 + lc] = wb;
    __syncthreads();
    #pragma unroll
    for (int kk = 0; kk < 4; kk++){
      uint4 a[4], b[4];
      #pragma unroll
      for (int m=0;m<4;m++) a[m] = *(const uint4*)&As[(ty*4+m)*20 + kk*4];
      #pragma unroll
      for (int n=0;n<4;n++) b[n] = *(const uint4*)&Bs[(tx*4+n)*20 + kk*4];
      #pragma unroll
      for (int m=0;m<4;m++)
        #pragma unroll
        for (int n=0;n<4;n++){
          int t = __dp4a((int)a[m].x, (int)b[n].x, acc[m][n]);
          t     = __dp4a((int)a[m].y, (int)b[n].y, t);
          t     = __dp4a((int)a[m].z, (int)b[n].z, t);
          acc[m][n] = __dp4a((int)a[m].w, (int)b[n].w, t);
        }
    }
    __syncthreads();
  }
  float mx = __uint_as_float(g_absmax[slot]);
  float scale = (mx / 128.0f) * g_wbeta[slot];   // dequant * beta
  #pragma unroll
  for (int m=0;m<4;m++)
    #pragma unroll
    for (int n=0;n<4;n++)
      C[(size_t)(m0+ty*4+m)*DM + (n0+tx*4+n)] = (float)acc[m][n] * scale;
}

__global__ void k_maskpack(const int* mask){
  int row = blockIdx.x;                 // b*2048 + q
  int lane = threadIdx.x & 31, wd = threadIdx.x >> 5;
  for (int w8 = 0; w8 < 8; w8++){
    int kk = w8*256 + threadIdx.x;
    int mv = mask[(size_t)row*2048 + kk];
    u32 bits = __ballot_sync(0xffffffffu, mv != 0);
    if (lane == 0) g_maskbits[(size_t)row*64 + w8*8 + wd] = bits;
  }
}

// Flash attention, fp32 via packed f32x2. One query per thread (q + acc in regs).
__global__ void __launch_bounds__(128,2) k_flash(){
  int qt = blockIdx.x & 15;
  int h  = (blockIdx.x >> 4) & 15;
  int b  = blockIdx.x >> 8;
  int q  = qt*128 + threadIdx.x;
  size_t qoff = ((size_t)(b*2048 + q))*DM + h*64;
  const float* QP = g_proj[0];
  const float* KP = g_proj[1];
  const float* VP = g_proj[2];

  ull q2[32];
  {
    const float4* qp = (const float4*)(QP + qoff);
    #pragma unroll
    for (int t=0;t<16;t++){
      float4 f = qp[t];
      q2[2*t]   = pk2(f.x*0.125f, f.y*0.125f);   // fold 1/sqrt(64) into q
      q2[2*t+1] = pk2(f.z*0.125f, f.w*0.125f);
    }
  }
  ull acc2[32];
  #pragma unroll
  for (int t=0;t<32;t++) acc2[t] = 0ull;
  float m = -1e30f, s = 0.f;

  __shared__ float ksh[64][64];
  __shared__ float vsh[64][64];
  const u32* mbase = g_maskbits + (size_t)(b*2048 + q)*64;

  for (int k0 = 0; k0 < 2048; k0 += 64){
    #pragma unroll
    for (int i = threadIdx.x; i < 64*16; i += 128){
      int row = i >> 4, c = (i & 15) * 4;
      size_t goff = ((size_t)(b*2048 + k0 + row))*DM + h*64 + c;
      *(float4*)&ksh[row][c] = *(const float4*)(KP + goff);
      *(float4*)&vsh[row][c] = *(const float4*)(VP + goff);
    }
    __syncthreads();

    for (int j0 = 0; j0 < 64; j0 += 8){
      u32 mb = mbase[(k0 + j0) >> 5] >> (j0 & 31);
      float lg[8];
      #pragma unroll
      for (int jj=0;jj<8;jj++){
        const ull* kp = (const ull*)&ksh[j0+jj][0];
        ull d0 = 0ull, d1 = 0ull;
        #pragma unroll
        for (int t=0;t<16;t++){
          d0 = f2fma(q2[2*t],   kp[2*t],   d0);
          d1 = f2fma(q2[2*t+1], kp[2*t+1], d1);
        }
        float2 dd = upk2(f2add(d0, d1));
        float lv = dd.x + dd.y;
        lg[jj] = ((mb >> jj) & 1u) ? lv : -1e9f;
      }
      float cm = lg[0];
      #pragma unroll
      for (int jj=1;jj<8;jj++) cm = fmaxf(cm, lg[jj]);
      float mn = fmaxf(m, cm);
      float r = expf(m - mn);
      float p[8]; float ps = 0.f;
      #pragma unroll
      for (int jj=0;jj<8;jj++){ p[jj] = expf(lg[jj] - mn); ps += p[jj]; }
      s = s * r + ps;
      ull rr = pk2(r, r);
      #pragma unroll
      for (int t=0;t<32;t++) acc2[t] = f2mul(acc2[t], rr);
      #pragma unroll
      for (int jj=0;jj<8;jj++){
        ull pp = pk2(p[jj], p[jj]);
        const ull* vp = (const ull*)&vsh[j0+jj][0];
        #pragma unroll
        for (int t=0;t<32;t++) acc2[t] = f2fma(pp, vp[t], acc2[t]);
      }
      m = mn;
    }
    __syncthreads();
  }
  float inv = 1.0f / s;
  float* orow = g_att + qoff;
  #pragma unroll
  for (int t=0;t<32;t++){
    float2 f = upk2(acc2[t]);
    orow[2*t]   = f.x * inv;
    orow[2*t+1] = f.y * inv;
  }
}

// ------------------------- launcher --------------------------------------
extern "C" void kernel_launch(void* const* d_in, const int* in_sizes, int n_in,
                              void* d_out, int out_size){
  const float* q   = (const float*)d_in[0];
  const float* k   = (const float*)d_in[1];
  const float* v   = (const float*)d_in[2];
  const int*  mask = (const int*)  d_in[3];
  const float* w0  = (const float*)d_in[4];  // wq_w
  const float* w1  = (const float*)d_in[5];  // wk_w
  const float* w2  = (const float*)d_in[6];  // wv_w
  const float* w3  = (const float*)d_in[7];  // w0_w
  float* out = (float*)d_out;

  k_init<<<1,32>>>();
  k_wstats1<<<dim3(256,4),256>>>(w0,w1,w2,w3);
  k_wstats2<<<4,256>>>();
  k_wquant<<<dim3(1024,4),256>>>(w0,w1,w2,w3);

  k_ln<<<4096,256>>>(q,0);
  k_ln<<<4096,256>>>(k,1);
  k_ln<<<4096,256>>>(v,2);
  k_quant<<<4096,256>>>(0);
  k_quant<<<4096,256>>>(1);
  k_quant<<<4096,256>>>(2);

  k_gemm<<<dim3(16,64,3),256>>>(nullptr,0);   // qp, kp, vp projections

  k_maskpack<<<4096,256>>>(mask);
  k_flash<<<512,128>>>();

  k_ln<<<4096,256>>>(nullptr,3);
  k_quant<<<4096,256>>>(3);
  k_gemm<<<dim3(16,64,1),256>>>(out,3);       // output projection -> d_out
}